// round 14
// baseline (speedup 1.0000x reference)
#include <cuda_runtime.h>
#include <cuda_fp16.h>
#include <cstdint>

#define N_NODES 50000
#define N_EDGES 1600000
#define G_GRAPHS 256
#define IN_CH 64
#define EC 32
#define H_CH 64
#define OUT_CH 10

#define NODE_HALF 28032   // alpha=0.56 split, multiple of 64

// ---------------- scratch ----------------
__device__ float  g_edge_aggr[N_NODES * EC];
__device__ __half g_y[N_NODES * H_CH];
__device__ float  g_yp[N_NODES * H_CH];   // layer-0 rel partial (x @ W1_rel[0:64])
__device__ float  g_u[N_NODES * H_CH];
__device__ float  g_agg[N_NODES * H_CH];
__device__ float  g_x[N_NODES * H_CH];
__device__ float  g_pooled[G_GRAPHS * H_CH];
__device__ int    g_icnt[2 * N_NODES];
__device__ int    g_off[N_NODES + 1];
__device__ int    g_csr[N_EDGES];

// ---------------- PTX helpers ----------------
__device__ __forceinline__ void red4(float* addr, float4 v) {
    asm volatile("red.global.add.v4.f32 [%0], {%1,%2,%3,%4};"
                 :: "l"(addr), "f"(v.x), "f"(v.y), "f"(v.z), "f"(v.w)
                 : "memory");
}
__device__ __forceinline__ void ffma2(unsigned long long& d,
                                      unsigned long long a, unsigned long long b) {
    asm("fma.rn.f32x2 %0, %1, %2, %0;" : "+l"(d) : "l"(a), "l"(b));
}
__device__ __forceinline__ unsigned long long bcast2(float a) {
    unsigned long long r;
    asm("mov.b64 %0, {%1, %1};" : "=l"(r) : "f"(a));
    return r;
}
__device__ __forceinline__ float2 u2f(unsigned long long v) {
    float2 f;
    asm("mov.b64 {%0, %1}, %2;" : "=f"(f.x), "=f"(f.y) : "l"(v));
    return f;
}

// ---------------- CSR build ----------------
__global__ void k_hist(const int* __restrict__ edge_index) {
    int e = blockIdx.x * blockDim.x + threadIdx.x;
    if (e >= N_EDGES) return;
    atomicAdd(&g_icnt[edge_index[N_EDGES + e]], 1);
}

__global__ void k_scan() {
    __shared__ int wsum[32];
    __shared__ int chunk_base;
    int tid = threadIdx.x, lane = tid & 31, wid = tid >> 5;
    if (tid == 0) chunk_base = 0;
    for (int start = 0; start < N_NODES; start += 4096) {
        __syncthreads();
        int idx = start + tid * 4;
        int a0 = 0, a1 = 0, a2 = 0, a3 = 0;
        if (idx + 3 < N_NODES) {
            int4 t = *reinterpret_cast<const int4*>(&g_icnt[idx]);
            a0 = t.x; a1 = t.y; a2 = t.z; a3 = t.w;
        } else if (idx < N_NODES) {
            a0 = g_icnt[idx];
            if (idx + 1 < N_NODES) a1 = g_icnt[idx + 1];
            if (idx + 2 < N_NODES) a2 = g_icnt[idx + 2];
        }
        int v = a0 + a1 + a2 + a3;
        int x = v;
#pragma unroll
        for (int d = 1; d < 32; d <<= 1) {
            int y = __shfl_up_sync(0xffffffffu, x, d);
            if (lane >= d) x += y;
        }
        if (lane == 31) wsum[wid] = x;
        __syncthreads();
        if (wid == 0) {
            int s = wsum[lane];
#pragma unroll
            for (int d = 1; d < 32; d <<= 1) {
                int y = __shfl_up_sync(0xffffffffu, s, d);
                if (lane >= d) s += y;
            }
            wsum[lane] = s;
        }
        __syncthreads();
        int wbase = (wid > 0) ? wsum[wid - 1] : 0;
        int base = chunk_base + wbase + x - v;
        if (idx < N_NODES)     g_off[idx]     = base;
        if (idx + 1 < N_NODES) g_off[idx + 1] = base + a0;
        if (idx + 2 < N_NODES) g_off[idx + 2] = base + a0 + a1;
        if (idx + 3 < N_NODES) g_off[idx + 3] = base + a0 + a1 + a2;
        __syncthreads();
        if (tid == 0) chunk_base += wsum[31];
    }
    __syncthreads();
    if (tid == 0) g_off[N_NODES] = chunk_base;
}

__global__ void k_fill(const int* __restrict__ edge_index) {
    int e = blockIdx.x * blockDim.x + threadIdx.x;
    if (e >= N_EDGES) return;
    int c = edge_index[N_EDGES + e];
    int pos = g_off[c] + atomicAdd(&g_icnt[N_NODES + c], 1);
    g_csr[pos] = edge_index[e];
}

// ---------------- edge_attr aggregation (R12: 4 edges/thread) ----------------
__global__ void k_edge_aggr(const float* __restrict__ edge_attr,
                            const int* __restrict__ edge_index,
                            float* __restrict__ out) {
    const int Q = N_EDGES / 4;
    int tid = blockIdx.x * blockDim.x + threadIdx.x;
    int e = tid >> 3, p4 = (tid & 7) * 4;
    if (e >= Q) return;
    int e1 = e + Q, e2 = e + 2 * Q, e3 = e + 3 * Q;
    int r0 = edge_index[e],  r1 = edge_index[e1];
    int r2 = edge_index[e2], r3 = edge_index[e3];
    float4 v0 = *reinterpret_cast<const float4*>(edge_attr + (size_t)e  * EC + p4);
    float4 v1 = *reinterpret_cast<const float4*>(edge_attr + (size_t)e1 * EC + p4);
    float4 v2 = *reinterpret_cast<const float4*>(edge_attr + (size_t)e2 * EC + p4);
    float4 v3 = *reinterpret_cast<const float4*>(edge_attr + (size_t)e3 * EC + p4);
    red4(out + (size_t)r0 * EC + p4, v0);
    red4(out + (size_t)r1 * EC + p4, v1);
    red4(out + (size_t)r2 * EC + p4, v2);
    red4(out + (size_t)r3 * EC + p4, v3);
}

// ---------------- CSR gather (R12): 8 threads/node, unroll 4, node-range ----------------
__global__ void k_gather(int node_base, int node_end) {
    int tid = threadIdx.x;
    int node = node_base + blockIdx.x * 32 + (tid >> 3);
    int p8 = (tid & 7) * 8;
    if (node >= node_end) return;
    int s = g_off[node], e = g_off[node + 1];
    float acc0[8], acc1[8];
#pragma unroll
    for (int j = 0; j < 8; j++) { acc0[j] = 0.f; acc1[j] = 0.f; }

    int i = s;
    for (; i + 4 <= e; i += 4) {
        int n0 = g_csr[i], n1 = g_csr[i + 1], n2 = g_csr[i + 2], n3 = g_csr[i + 3];
        uint4 v0 = *reinterpret_cast<const uint4*>(&g_y[(size_t)n0 * H_CH + p8]);
        uint4 v1 = *reinterpret_cast<const uint4*>(&g_y[(size_t)n1 * H_CH + p8]);
        uint4 v2 = *reinterpret_cast<const uint4*>(&g_y[(size_t)n2 * H_CH + p8]);
        uint4 v3 = *reinterpret_cast<const uint4*>(&g_y[(size_t)n3 * H_CH + p8]);
        const __half2* h0 = reinterpret_cast<const __half2*>(&v0);
        const __half2* h1 = reinterpret_cast<const __half2*>(&v1);
        const __half2* h2 = reinterpret_cast<const __half2*>(&v2);
        const __half2* h3 = reinterpret_cast<const __half2*>(&v3);
#pragma unroll
        for (int q = 0; q < 4; q++) {
            float2 f0 = __half22float2(h0[q]);
            float2 f1 = __half22float2(h1[q]);
            float2 f2 = __half22float2(h2[q]);
            float2 f3 = __half22float2(h3[q]);
            acc0[q * 2]     += f0.x + f2.x;
            acc0[q * 2 + 1] += f0.y + f2.y;
            acc1[q * 2]     += f1.x + f3.x;
            acc1[q * 2 + 1] += f1.y + f3.y;
        }
    }
    for (; i < e; i++) {
        int n0 = g_csr[i];
        uint4 v0 = *reinterpret_cast<const uint4*>(&g_y[(size_t)n0 * H_CH + p8]);
        const __half2* h0 = reinterpret_cast<const __half2*>(&v0);
#pragma unroll
        for (int q = 0; q < 4; q++) {
            float2 f0 = __half22float2(h0[q]);
            acc0[q * 2]     += f0.x;
            acc0[q * 2 + 1] += f0.y;
        }
    }
    float4 o0 = make_float4(acc0[0] + acc1[0], acc0[1] + acc1[1],
                            acc0[2] + acc1[2], acc0[3] + acc1[3]);
    float4 o1 = make_float4(acc0[4] + acc1[4], acc0[5] + acc1[5],
                            acc0[6] + acc1[6], acc0[7] + acc1[7]);
    *reinterpret_cast<float4*>(&g_agg[(size_t)node * H_CH + p8])     = o0;
    *reinterpret_cast<float4*>(&g_agg[(size_t)node * H_CH + p8 + 4]) = o1;
}

// ---------------- layer-0 rel part A: g_yp = x @ W1_rel[0:64] (fp32) ----------------
__global__ void k_mlp1a_rel(const float* __restrict__ x_in,
                            const float* __restrict__ W1_rel) {
    extern __shared__ float sm[];
    float* xs = sm;              // [64][68]
    float* Ws = sm + 64 * 68;    // [64][64]
    const int tid = threadIdx.x;
    const int node0 = blockIdx.x * 64;

    for (int i = tid; i < 64 * 64; i += 256) Ws[i] = W1_rel[i];
    for (int i = tid; i < 64 * 64; i += 256) {
        int n = i >> 6, k = i & 63;
        int node = node0 + n;
        xs[n * 68 + k] = (node < N_NODES) ? x_in[(size_t)node * 64 + k] : 0.f;
    }
    __syncthreads();

    const int og = tid & 15, ng = tid >> 4;
    const int j0 = og * 4, n0 = ng * 4;
    unsigned long long acc[4][2];
#pragma unroll
    for (int i = 0; i < 4; i++) { acc[i][0] = 0ull; acc[i][1] = 0ull; }

    for (int k4 = 0; k4 < 64; k4 += 4) {
        float4 a0 = *reinterpret_cast<const float4*>(&xs[(n0 + 0) * 68 + k4]);
        float4 a1 = *reinterpret_cast<const float4*>(&xs[(n0 + 1) * 68 + k4]);
        float4 a2 = *reinterpret_cast<const float4*>(&xs[(n0 + 2) * 68 + k4]);
        float4 a3 = *reinterpret_cast<const float4*>(&xs[(n0 + 3) * 68 + k4]);
        const float* p0 = &a0.x;
        const float* p1 = &a1.x;
        const float* p2 = &a2.x;
        const float* p3 = &a3.x;
#pragma unroll
        for (int j = 0; j < 4; j++) {
            ulonglong2 w = *reinterpret_cast<const ulonglong2*>(&Ws[(k4 + j) * 64 + j0]);
            unsigned long long b0 = bcast2(p0[j]);
            unsigned long long b1 = bcast2(p1[j]);
            unsigned long long b2 = bcast2(p2[j]);
            unsigned long long b3 = bcast2(p3[j]);
            ffma2(acc[0][0], b0, w.x);  ffma2(acc[0][1], b0, w.y);
            ffma2(acc[1][0], b1, w.x);  ffma2(acc[1][1], b1, w.y);
            ffma2(acc[2][0], b2, w.x);  ffma2(acc[2][1], b2, w.y);
            ffma2(acc[3][0], b3, w.x);  ffma2(acc[3][1], b3, w.y);
        }
    }

#pragma unroll
    for (int i = 0; i < 4; i++) {
        int node = node0 + n0 + i;
        if (node >= N_NODES) continue;
        float2 f0 = u2f(acc[i][0]), f1 = u2f(acc[i][1]);
        *reinterpret_cast<float4*>(&g_yp[(size_t)node * 64 + j0]) =
            make_float4(f0.x, f0.y, f1.x, f1.y);
    }
}

// ---------------- layer-0 rel part B: g_y = fp16(g_yp + ea @ W1_rel[64:96]) ----------------
__global__ void k_mlp1b_rel(const float* __restrict__ W1_rel) {
    extern __shared__ float sm[];
    float* xs = sm;              // [64][36]
    float* Ws = sm + 64 * 36;    // [32][64]
    const int tid = threadIdx.x;
    const int node0 = blockIdx.x * 64;

    for (int i = tid; i < 32 * 64; i += 256) Ws[i] = W1_rel[64 * 64 + i];
    for (int i = tid; i < 64 * 32; i += 256) {
        int n = i >> 5, k = i & 31;
        int node = node0 + n;
        xs[n * 36 + k] = (node < N_NODES) ? g_edge_aggr[(size_t)node * EC + k] : 0.f;
    }
    __syncthreads();

    const int og = tid & 15, ng = tid >> 4;
    const int j0 = og * 4, n0 = ng * 4;
    unsigned long long acc[4][2];
#pragma unroll
    for (int i = 0; i < 4; i++) { acc[i][0] = 0ull; acc[i][1] = 0ull; }

    for (int k4 = 0; k4 < 32; k4 += 4) {
        float4 a0 = *reinterpret_cast<const float4*>(&xs[(n0 + 0) * 36 + k4]);
        float4 a1 = *reinterpret_cast<const float4*>(&xs[(n0 + 1) * 36 + k4]);
        float4 a2 = *reinterpret_cast<const float4*>(&xs[(n0 + 2) * 36 + k4]);
        float4 a3 = *reinterpret_cast<const float4*>(&xs[(n0 + 3) * 36 + k4]);
        const float* p0 = &a0.x;
        const float* p1 = &a1.x;
        const float* p2 = &a2.x;
        const float* p3 = &a3.x;
#pragma unroll
        for (int j = 0; j < 4; j++) {
            ulonglong2 w = *reinterpret_cast<const ulonglong2*>(&Ws[(k4 + j) * 64 + j0]);
            unsigned long long b0 = bcast2(p0[j]);
            unsigned long long b1 = bcast2(p1[j]);
            unsigned long long b2 = bcast2(p2[j]);
            unsigned long long b3 = bcast2(p3[j]);
            ffma2(acc[0][0], b0, w.x);  ffma2(acc[0][1], b0, w.y);
            ffma2(acc[1][0], b1, w.x);  ffma2(acc[1][1], b1, w.y);
            ffma2(acc[2][0], b2, w.x);  ffma2(acc[2][1], b2, w.y);
            ffma2(acc[3][0], b3, w.x);  ffma2(acc[3][1], b3, w.y);
        }
    }

#pragma unroll
    for (int i = 0; i < 4; i++) {
        int node = node0 + n0 + i;
        if (node >= N_NODES) continue;
        float4 p = *reinterpret_cast<const float4*>(&g_yp[(size_t)node * 64 + j0]);
        float2 f0 = u2f(acc[i][0]), f1 = u2f(acc[i][1]);
        __half2 h0 = __floats2half2_rn(p.x + f0.x, p.y + f0.y);
        __half2 h1 = __floats2half2_rn(p.z + f1.x, p.w + f1.y);
        uint2 pk;
        pk.x = *reinterpret_cast<unsigned int*>(&h0);
        pk.y = *reinterpret_cast<unsigned int*>(&h1);
        *reinterpret_cast<uint2*>(&g_y[(size_t)node * 64 + j0]) = pk;
    }
}

// ---------------- mlp1 rel (fused, layer 1): g_y(fp16) = xc @ W1_rel, node-range ----------------
__global__ void k_mlp1_rel(const float* __restrict__ x_in,
                           const float* __restrict__ W1_rel,
                           int node_base) {
    extern __shared__ float sm[];
    float* xs = sm;              // [64][96]
    float* Ws = sm + 64 * 96;    // [96][64]
    const int tid = threadIdx.x;
    const int node0 = node_base + blockIdx.x * 64;

    for (int i = tid; i < 96 * 64; i += 256) Ws[i] = W1_rel[i];
    for (int i = tid; i < 64 * 96; i += 256) {
        int n = i / 96, k = i - n * 96;
        int node = node0 + n;
        float v = 0.f;
        if (node < N_NODES)
            v = (k < 64) ? x_in[(size_t)node * 64 + k]
                         : g_edge_aggr[(size_t)node * EC + (k - 64)];
        xs[i] = v;
    }
    __syncthreads();

    const int og = tid & 15, ng = tid >> 4;
    const int j0 = og * 4, n0 = ng * 4;
    unsigned long long acc[4][2];
#pragma unroll
    for (int i = 0; i < 4; i++) { acc[i][0] = 0ull; acc[i][1] = 0ull; }

    for (int k4 = 0; k4 < 96; k4 += 4) {
        float4 a0 = *reinterpret_cast<const float4*>(&xs[(n0 + 0) * 96 + k4]);
        float4 a1 = *reinterpret_cast<const float4*>(&xs[(n0 + 1) * 96 + k4]);
        float4 a2 = *reinterpret_cast<const float4*>(&xs[(n0 + 2) * 96 + k4]);
        float4 a3 = *reinterpret_cast<const float4*>(&xs[(n0 + 3) * 96 + k4]);
        const float* p0 = &a0.x;
        const float* p1 = &a1.x;
        const float* p2 = &a2.x;
        const float* p3 = &a3.x;
#pragma unroll
        for (int j = 0; j < 4; j++) {
            ulonglong2 w = *reinterpret_cast<const ulonglong2*>(&Ws[(k4 + j) * 64 + j0]);
            unsigned long long b0 = bcast2(p0[j]);
            unsigned long long b1 = bcast2(p1[j]);
            unsigned long long b2 = bcast2(p2[j]);
            unsigned long long b3 = bcast2(p3[j]);
            ffma2(acc[0][0], b0, w.x);  ffma2(acc[0][1], b0, w.y);
            ffma2(acc[1][0], b1, w.x);  ffma2(acc[1][1], b1, w.y);
            ffma2(acc[2][0], b2, w.x);  ffma2(acc[2][1], b2, w.y);
            ffma2(acc[3][0], b3, w.x);  ffma2(acc[3][1], b3, w.y);
        }
    }

#pragma unroll
    for (int i = 0; i < 4; i++) {
        int node = node0 + n0 + i;
        if (node >= N_NODES) continue;
        float2 f0 = u2f(acc[i][0]), f1 = u2f(acc[i][1]);
        __half2 h0 = __floats2half2_rn(f0.x, f0.y);
        __half2 h1 = __floats2half2_rn(f1.x, f1.y);
        uint2 pk;
        pk.x = *reinterpret_cast<unsigned int*>(&h0);
        pk.y = *reinterpret_cast<unsigned int*>(&h1);
        *reinterpret_cast<uint2*>(&g_y[(size_t)node * 64 + j0]) = pk;
    }
}

// ---------------- mlp1 root: g_u = relu(xc @ W1_root + b1) ----------------
__global__ void k_mlp1_root(const float* __restrict__ x_in,
                            const float* __restrict__ W1_root,
                            const float* __restrict__ b1_root) {
    extern __shared__ float sm[];
    float* xs = sm;              // [64][96]
    float* Ws = sm + 64 * 96;    // [96][64]
    float* b1 = Ws + 96 * 64;    // [64]
    const int tid = threadIdx.x;
    const int node0 = blockIdx.x * 64;

    for (int i = tid; i < 96 * 64; i += 256) Ws[i] = W1_root[i];
    if (tid < 64) b1[tid] = b1_root[tid];
    for (int i = tid; i < 64 * 96; i += 256) {
        int n = i / 96, k = i - n * 96;
        int node = node0 + n;
        float v = 0.f;
        if (node < N_NODES)
            v = (k < 64) ? x_in[(size_t)node * 64 + k]
                         : g_edge_aggr[(size_t)node * EC + (k - 64)];
        xs[i] = v;
    }
    __syncthreads();

    const int og = tid & 15, ng = tid >> 4;
    const int j0 = og * 4, n0 = ng * 4;
    unsigned long long acc[4][2];
#pragma unroll
    for (int i = 0; i < 4; i++) { acc[i][0] = 0ull; acc[i][1] = 0ull; }

    for (int k4 = 0; k4 < 96; k4 += 4) {
        float4 a0 = *reinterpret_cast<const float4*>(&xs[(n0 + 0) * 96 + k4]);
        float4 a1 = *reinterpret_cast<const float4*>(&xs[(n0 + 1) * 96 + k4]);
        float4 a2 = *reinterpret_cast<const float4*>(&xs[(n0 + 2) * 96 + k4]);
        float4 a3 = *reinterpret_cast<const float4*>(&xs[(n0 + 3) * 96 + k4]);
        const float* p0 = &a0.x;
        const float* p1 = &a1.x;
        const float* p2 = &a2.x;
        const float* p3 = &a3.x;
#pragma unroll
        for (int j = 0; j < 4; j++) {
            ulonglong2 w = *reinterpret_cast<const ulonglong2*>(&Ws[(k4 + j) * 64 + j0]);
            unsigned long long b0 = bcast2(p0[j]);
            unsigned long long b1x = bcast2(p1[j]);
            unsigned long long b2 = bcast2(p2[j]);
            unsigned long long b3 = bcast2(p3[j]);
            ffma2(acc[0][0], b0, w.x);   ffma2(acc[0][1], b0, w.y);
            ffma2(acc[1][0], b1x, w.x);  ffma2(acc[1][1], b1x, w.y);
            ffma2(acc[2][0], b2, w.x);   ffma2(acc[2][1], b2, w.y);
            ffma2(acc[3][0], b3, w.x);   ffma2(acc[3][1], b3, w.y);
        }
    }

#pragma unroll
    for (int i = 0; i < 4; i++) {
        int node = node0 + n0 + i;
        if (node >= N_NODES) continue;
        float2 f0 = u2f(acc[i][0]), f1 = u2f(acc[i][1]);
        float4 o = make_float4(fmaxf(f0.x + b1[j0 + 0], 0.f),
                               fmaxf(f0.y + b1[j0 + 1], 0.f),
                               fmaxf(f1.x + b1[j0 + 2], 0.f),
                               fmaxf(f1.y + b1[j0 + 3], 0.f));
        *reinterpret_cast<float4*>(&g_u[(size_t)node * 64 + j0]) = o;
    }
}

// ---------------- mlp2: node-range + fused pooling on last layer ----------------
__global__ void k_node_mlp2(const float* __restrict__ b1_rel,
                            const float* __restrict__ W2_rel,
                            const float* __restrict__ W2_root,
                            const float* __restrict__ b2_rel,
                            const float* __restrict__ b2_root,
                            const int* __restrict__ batch,
                            int final_layer, int node_base) {
    extern __shared__ float sm[];
    float* As = sm;               // [64][128]
    float* Ws = sm + 64 * 128;    // [128][64]
    float* b2 = Ws + 128 * 64;    // [64]
    const int tid = threadIdx.x;
    const int node0 = node_base + blockIdx.x * 64;

    for (int i = tid; i < 128 * 64; i += 256)
        Ws[i] = (i < 64 * 64) ? W2_rel[i] : W2_root[i - 64 * 64];
    if (tid < 64) b2[tid] = b2_rel[tid] + b2_root[tid];
    for (int i = tid; i < 64 * 128; i += 256) {
        int n = i >> 7, k = i & 127;
        int node = node0 + n;
        float v = 0.f;
        if (node < N_NODES) {
            if (k < 64) v = fmaxf(g_agg[(size_t)node * 64 + k] + __ldg(&b1_rel[k]), 0.f);
            else        v = g_u[(size_t)node * 64 + (k - 64)];
        }
        As[i] = v;
    }
    __syncthreads();

    const int og = tid & 15, ng = tid >> 4;
    const int j0 = og * 4, n0 = ng * 4;
    unsigned long long acc[4][2];
#pragma unroll
    for (int i = 0; i < 4; i++) { acc[i][0] = 0ull; acc[i][1] = 0ull; }

    for (int k4 = 0; k4 < 128; k4 += 4) {
        float4 a0 = *reinterpret_cast<const float4*>(&As[(n0 + 0) * 128 + k4]);
        float4 a1 = *reinterpret_cast<const float4*>(&As[(n0 + 1) * 128 + k4]);
        float4 a2 = *reinterpret_cast<const float4*>(&As[(n0 + 2) * 128 + k4]);
        float4 a3 = *reinterpret_cast<const float4*>(&As[(n0 + 3) * 128 + k4]);
        const float* p0 = &a0.x;
        const float* p1 = &a1.x;
        const float* p2 = &a2.x;
        const float* p3 = &a3.x;
#pragma unroll
        for (int j = 0; j < 4; j++) {
            ulonglong2 w = *reinterpret_cast<const ulonglong2*>(&Ws[(k4 + j) * 64 + j0]);
            unsigned long long b0 = bcast2(p0[j]);
            unsigned long long b1 = bcast2(p1[j]);
            unsigned long long b2x = bcast2(p2[j]);
            unsigned long long b3 = bcast2(p3[j]);
            ffma2(acc[0][0], b0, w.x);   ffma2(acc[0][1], b0, w.y);
            ffma2(acc[1][0], b1, w.x);   ffma2(acc[1][1], b1, w.y);
            ffma2(acc[2][0], b2x, w.x);  ffma2(acc[2][1], b2x, w.y);
            ffma2(acc[3][0], b3, w.x);   ffma2(acc[3][1], b3, w.y);
        }
    }

#pragma unroll
    for (int i = 0; i < 4; i++) {
        int node = node0 + n0 + i;
        if (node >= N_NODES) continue;
        float2 f0 = u2f(acc[i][0]), f1 = u2f(acc[i][1]);
        float4 o = make_float4(fmaxf(f0.x + b2[j0 + 0], 0.f),
                               fmaxf(f0.y + b2[j0 + 1], 0.f),
                               fmaxf(f1.x + b2[j0 + 2], 0.f),
                               fmaxf(f1.y + b2[j0 + 3], 0.f));
        if (final_layer) {
            int b = batch[node];
            red4(&g_pooled[(size_t)b * 64 + j0], o);
        } else {
            *reinterpret_cast<float4*>(&g_x[(size_t)node * 64 + j0]) = o;
        }
    }
}

// ---------------- final MLP ----------------
__global__ void k_final(const float* __restrict__ W1, const float* __restrict__ b1,
                        const float* __restrict__ W2, const float* __restrict__ b2,
                        float* __restrict__ out) {
    __shared__ float pr[64];
    __shared__ float h[64];
    int g = blockIdx.x;
    int j = threadIdx.x;
    pr[j] = g_pooled[g * 64 + j];
    __syncthreads();
    float s = b1[j];
#pragma unroll 8
    for (int k = 0; k < 64; k++) s = fmaf(pr[k], W1[k * 64 + j], s);
    h[j] = fmaxf(s, 0.f);
    __syncthreads();
    if (j < OUT_CH) {
        float s2 = b2[j];
#pragma unroll 8
        for (int k = 0; k < 64; k++) s2 = fmaf(h[k], W2[k * OUT_CH + j], s2);
        out[g * OUT_CH + j] = s2;
    }
}

// ---------------- launch ----------------
extern "C" void kernel_launch(void* const* d_in, const int* in_sizes, int n_in,
                              void* d_out, int out_size) {
    const float* x         = (const float*)d_in[0];
    const float* edge_attr = (const float*)d_in[1];
    const float* relW1[2]  = {(const float*)d_in[2],  (const float*)d_in[10]};
    const float* relb1[2]  = {(const float*)d_in[3],  (const float*)d_in[11]};
    const float* relW2[2]  = {(const float*)d_in[4],  (const float*)d_in[12]};
    const float* relb2[2]  = {(const float*)d_in[5],  (const float*)d_in[13]};
    const float* rootW1[2] = {(const float*)d_in[6],  (const float*)d_in[14]};
    const float* rootb1[2] = {(const float*)d_in[7],  (const float*)d_in[15]};
    const float* rootW2[2] = {(const float*)d_in[8],  (const float*)d_in[16]};
    const float* rootb2[2] = {(const float*)d_in[9],  (const float*)d_in[17]};
    const float* finW1 = (const float*)d_in[18];
    const float* finb1 = (const float*)d_in[19];
    const float* finW2 = (const float*)d_in[20];
    const float* finb2 = (const float*)d_in[21];
    const int* edge_index = (const int*)d_in[22];
    const int* batch      = (const int*)d_in[23];
    float* out = (float*)d_out;

    float *p_ea, *p_x, *p_pooled;
    int *p_icnt;
    cudaGetSymbolAddress((void**)&p_ea, g_edge_aggr);
    cudaGetSymbolAddress((void**)&p_x, g_x);
    cudaGetSymbolAddress((void**)&p_pooled, g_pooled);
    cudaGetSymbolAddress((void**)&p_icnt, g_icnt);

    const int SMEM_REL  = (64 * 96 + 96 * 64) * 4;
    const int SMEM_A    = (64 * 68 + 64 * 64) * 4;     // 33792
    const int SMEM_B    = (64 * 36 + 32 * 64) * 4;     // 17408
    const int SMEM_ROOT = (64 * 96 + 96 * 64 + 64) * 4;
    const int SMEM2     = (64 * 128 + 128 * 64 + 64) * 4;
    cudaFuncSetAttribute(k_mlp1_rel, cudaFuncAttributeMaxDynamicSharedMemorySize, SMEM_REL);
    cudaFuncSetAttribute(k_mlp1a_rel, cudaFuncAttributeMaxDynamicSharedMemorySize, SMEM_A);
    cudaFuncSetAttribute(k_mlp1b_rel, cudaFuncAttributeMaxDynamicSharedMemorySize, SMEM_B);
    cudaFuncSetAttribute(k_mlp1_root, cudaFuncAttributeMaxDynamicSharedMemorySize, SMEM_ROOT);
    cudaFuncSetAttribute(k_node_mlp2, cudaFuncAttributeMaxDynamicSharedMemorySize, SMEM2);

    static cudaStream_t s2 = nullptr;
    static cudaEvent_t ev[12];
    if (!s2) {
        cudaStreamCreateWithFlags(&s2, cudaStreamNonBlocking);
        for (int i = 0; i < 12; i++)
            cudaEventCreateWithFlags(&ev[i], cudaEventDisableTiming);
    }
    cudaEvent_t evF = ev[0], evJ = ev[1], evA = ev[11],
                evY0 = ev[2], evU0 = ev[3], evGB0 = ev[4],
                evXA0 = ev[5], evX0 = ev[6],
                evRA1 = ev[7], evYB1 = ev[8], evU1 = ev[9], evGB1 = ev[10];

    const int NODE_BLOCKS = (N_NODES + 63) / 64;                  // 782
    const int REL_A = NODE_HALF / 64;                              // 438
    const int REL_B = (N_NODES - NODE_HALF + 63) / 64;             // 344
    const int MLP2_A = REL_A, MLP2_B = REL_B;
    const int GA = NODE_HALF / 32;                                 // 876
    const int GB = (N_NODES - NODE_HALF + 31) / 32;                // 687
    const int EDGE_BLOCKS = (N_EDGES + 255) / 256;

    // ---- fork: mlp1a (x-only rel partial) then CSR build on side stream ----
    cudaEventRecord(evF, 0);
    cudaStreamWaitEvent(s2, evF, 0);
    k_mlp1a_rel<<<NODE_BLOCKS, 256, SMEM_A, s2>>>(x, relW1[0]);
    cudaEventRecord(evA, s2);
    cudaMemsetAsync(p_icnt, 0, 2 * N_NODES * sizeof(int), s2);
    k_hist<<<EDGE_BLOCKS, 256, 0, s2>>>(edge_index);
    k_scan<<<1, 1024, 0, s2>>>();
    k_fill<<<EDGE_BLOCKS, 256, 0, s2>>>(edge_index);
    cudaEventRecord(evJ, s2);

    // ---- main prologue ----
    cudaMemsetAsync(p_ea, 0, N_NODES * EC * sizeof(float), 0);
    cudaMemsetAsync(p_pooled, 0, G_GRAPHS * H_CH * sizeof(float), 0);
    k_edge_aggr<<<(N_EDGES / 4 * 8 + 255) / 256, 256>>>(edge_attr, edge_index, p_ea);

    // ======== layer 0 ========
    cudaStreamWaitEvent(0, evA, 0);
    k_mlp1b_rel<<<NODE_BLOCKS, 256, SMEM_B>>>(relW1[0]);
    cudaEventRecord(evY0, 0);

    // s2: root(l0) then gatherB(l0)
    cudaStreamWaitEvent(s2, evY0, 0);
    k_mlp1_root<<<NODE_BLOCKS, 256, SMEM_ROOT, s2>>>(x, rootW1[0], rootb1[0]);
    cudaEventRecord(evU0, s2);
    k_gather<<<GB, 256, 0, s2>>>(NODE_HALF, N_NODES);
    cudaEventRecord(evGB0, s2);

    // main: gatherA(l0) + mlp2A(l0) + mlp2B(l0)
    cudaStreamWaitEvent(0, evJ, 0);
    k_gather<<<GA, 256>>>(0, NODE_HALF);
    cudaStreamWaitEvent(0, evU0, 0);
    k_node_mlp2<<<MLP2_A, 256, SMEM2>>>(relb1[0], relW2[0], rootW2[0],
                                        relb2[0], rootb2[0], batch, 0, 0);
    cudaEventRecord(evXA0, 0);
    cudaStreamWaitEvent(0, evGB0, 0);
    k_node_mlp2<<<MLP2_B, 256, SMEM2>>>(relb1[0], relW2[0], rootW2[0],
                                        relb2[0], rootb2[0], batch, 0, NODE_HALF);
    cudaEventRecord(evX0, 0);

    // ======== layer 1 ========
    // s2: relA(l1) hidden under main's mlp2B(l0)
    cudaStreamWaitEvent(s2, evXA0, 0);
    k_mlp1_rel<<<REL_A, 256, SMEM_REL, s2>>>(p_x, relW1[1], 0);
    cudaEventRecord(evRA1, s2);
    // s2: root(l1) then gatherB(l1)
    cudaStreamWaitEvent(s2, evX0, 0);
    k_mlp1_root<<<NODE_BLOCKS, 256, SMEM_ROOT, s2>>>(p_x, rootW1[1], rootb1[1]);
    cudaEventRecord(evU1, s2);

    // main: relB(l1)
    k_mlp1_rel<<<REL_B, 256, SMEM_REL>>>(p_x, relW1[1], NODE_HALF);
    cudaEventRecord(evYB1, 0);

    // s2: gatherB(l1) needs relA (in-order) + relB (evYB1)
    cudaStreamWaitEvent(s2, evYB1, 0);
    k_gather<<<GB, 256, 0, s2>>>(NODE_HALF, N_NODES);
    cudaEventRecord(evGB1, s2);

    // main: gatherA(l1) needs relA (evRA1) + relB (in-order)
    cudaStreamWaitEvent(0, evRA1, 0);
    k_gather<<<GA, 256>>>(0, NODE_HALF);
    cudaStreamWaitEvent(0, evU1, 0);
    k_node_mlp2<<<MLP2_A, 256, SMEM2>>>(relb1[1], relW2[1], rootW2[1],
                                        relb2[1], rootb2[1], batch, 1, 0);
    cudaStreamWaitEvent(0, evGB1, 0);
    k_node_mlp2<<<MLP2_B, 256, SMEM2>>>(relb1[1], relW2[1], rootW2[1],
                                        relb2[1], rootb2[1], batch, 1, NODE_HALF);

    k_final<<<G_GRAPHS, 64>>>(finW1, finb1, finW2, finb2, out);
}

// round 15
// speedup vs baseline: 1.1074x; 1.1074x over previous
#include <cuda_runtime.h>
#include <cuda_fp16.h>
#include <cstdint>

#define N_NODES 50000
#define N_EDGES 1600000
#define G_GRAPHS 256
#define IN_CH 64
#define EC 32
#define H_CH 64
#define OUT_CH 10

#define NODE_HALF 28032   // alpha=0.56 split, multiple of 64

// ---------------- scratch ----------------
__device__ float  g_edge_aggr[N_NODES * EC];
__device__ __half g_y[N_NODES * H_CH];
__device__ float  g_u[N_NODES * H_CH];
__device__ float  g_agg[N_NODES * H_CH];
__device__ float  g_x[N_NODES * H_CH];
__device__ float  g_pooled[G_GRAPHS * H_CH];
__device__ int    g_icnt[2 * N_NODES];
__device__ int    g_off[N_NODES + 1];
__device__ int    g_csr[N_EDGES];

// ---------------- PTX helpers ----------------
__device__ __forceinline__ void red4(float* addr, float4 v) {
    asm volatile("red.global.add.v4.f32 [%0], {%1,%2,%3,%4};"
                 :: "l"(addr), "f"(v.x), "f"(v.y), "f"(v.z), "f"(v.w)
                 : "memory");
}
__device__ __forceinline__ void ffma2(unsigned long long& d,
                                      unsigned long long a, unsigned long long b) {
    asm("fma.rn.f32x2 %0, %1, %2, %0;" : "+l"(d) : "l"(a), "l"(b));
}
__device__ __forceinline__ unsigned long long bcast2(float a) {
    unsigned long long r;
    asm("mov.b64 %0, {%1, %1};" : "=l"(r) : "f"(a));
    return r;
}
__device__ __forceinline__ float2 u2f(unsigned long long v) {
    float2 f;
    asm("mov.b64 {%0, %1}, %2;" : "=f"(f.x), "=f"(f.y) : "l"(v));
    return f;
}

// ---------------- CSR build ----------------
__global__ void k_hist(const int* __restrict__ edge_index) {
    int e = blockIdx.x * blockDim.x + threadIdx.x;
    if (e >= N_EDGES) return;
    atomicAdd(&g_icnt[edge_index[N_EDGES + e]], 1);
}

__global__ void k_scan() {
    __shared__ int wsum[32];
    __shared__ int chunk_base;
    int tid = threadIdx.x, lane = tid & 31, wid = tid >> 5;
    if (tid == 0) chunk_base = 0;
    for (int start = 0; start < N_NODES; start += 4096) {
        __syncthreads();
        int idx = start + tid * 4;
        int a0 = 0, a1 = 0, a2 = 0, a3 = 0;
        if (idx + 3 < N_NODES) {
            int4 t = *reinterpret_cast<const int4*>(&g_icnt[idx]);
            a0 = t.x; a1 = t.y; a2 = t.z; a3 = t.w;
        } else if (idx < N_NODES) {
            a0 = g_icnt[idx];
            if (idx + 1 < N_NODES) a1 = g_icnt[idx + 1];
            if (idx + 2 < N_NODES) a2 = g_icnt[idx + 2];
        }
        int v = a0 + a1 + a2 + a3;
        int x = v;
#pragma unroll
        for (int d = 1; d < 32; d <<= 1) {
            int y = __shfl_up_sync(0xffffffffu, x, d);
            if (lane >= d) x += y;
        }
        if (lane == 31) wsum[wid] = x;
        __syncthreads();
        if (wid == 0) {
            int s = wsum[lane];
#pragma unroll
            for (int d = 1; d < 32; d <<= 1) {
                int y = __shfl_up_sync(0xffffffffu, s, d);
                if (lane >= d) s += y;
            }
            wsum[lane] = s;
        }
        __syncthreads();
        int wbase = (wid > 0) ? wsum[wid - 1] : 0;
        int base = chunk_base + wbase + x - v;
        if (idx < N_NODES)     g_off[idx]     = base;
        if (idx + 1 < N_NODES) g_off[idx + 1] = base + a0;
        if (idx + 2 < N_NODES) g_off[idx + 2] = base + a0 + a1;
        if (idx + 3 < N_NODES) g_off[idx + 3] = base + a0 + a1 + a2;
        __syncthreads();
        if (tid == 0) chunk_base += wsum[31];
    }
    __syncthreads();
    if (tid == 0) g_off[N_NODES] = chunk_base;
}

__global__ void k_fill(const int* __restrict__ edge_index) {
    int e = blockIdx.x * blockDim.x + threadIdx.x;
    if (e >= N_EDGES) return;
    int c = edge_index[N_EDGES + e];
    int pos = g_off[c] + atomicAdd(&g_icnt[N_NODES + c], 1);
    g_csr[pos] = edge_index[e];
}

// ---------------- edge_attr aggregation (4 edges/thread) ----------------
__global__ void k_edge_aggr(const float* __restrict__ edge_attr,
                            const int* __restrict__ edge_index,
                            float* __restrict__ out) {
    const int Q = N_EDGES / 4;
    int tid = blockIdx.x * blockDim.x + threadIdx.x;
    int e = tid >> 3, p4 = (tid & 7) * 4;
    if (e >= Q) return;
    int e1 = e + Q, e2 = e + 2 * Q, e3 = e + 3 * Q;
    int r0 = edge_index[e],  r1 = edge_index[e1];
    int r2 = edge_index[e2], r3 = edge_index[e3];
    float4 v0 = *reinterpret_cast<const float4*>(edge_attr + (size_t)e  * EC + p4);
    float4 v1 = *reinterpret_cast<const float4*>(edge_attr + (size_t)e1 * EC + p4);
    float4 v2 = *reinterpret_cast<const float4*>(edge_attr + (size_t)e2 * EC + p4);
    float4 v3 = *reinterpret_cast<const float4*>(edge_attr + (size_t)e3 * EC + p4);
    red4(out + (size_t)r0 * EC + p4, v0);
    red4(out + (size_t)r1 * EC + p4, v1);
    red4(out + (size_t)r2 * EC + p4, v2);
    red4(out + (size_t)r3 * EC + p4, v3);
}

// ---------------- CSR gather: 8 threads/node, unroll 4, node-range ----------------
__global__ void k_gather(int node_base, int node_end) {
    int tid = threadIdx.x;
    int node = node_base + blockIdx.x * 32 + (tid >> 3);
    int p8 = (tid & 7) * 8;
    if (node >= node_end) return;
    int s = g_off[node], e = g_off[node + 1];
    float acc0[8], acc1[8];
#pragma unroll
    for (int j = 0; j < 8; j++) { acc0[j] = 0.f; acc1[j] = 0.f; }

    int i = s;
    for (; i + 4 <= e; i += 4) {
        int n0 = g_csr[i], n1 = g_csr[i + 1], n2 = g_csr[i + 2], n3 = g_csr[i + 3];
        uint4 v0 = *reinterpret_cast<const uint4*>(&g_y[(size_t)n0 * H_CH + p8]);
        uint4 v1 = *reinterpret_cast<const uint4*>(&g_y[(size_t)n1 * H_CH + p8]);
        uint4 v2 = *reinterpret_cast<const uint4*>(&g_y[(size_t)n2 * H_CH + p8]);
        uint4 v3 = *reinterpret_cast<const uint4*>(&g_y[(size_t)n3 * H_CH + p8]);
        const __half2* h0 = reinterpret_cast<const __half2*>(&v0);
        const __half2* h1 = reinterpret_cast<const __half2*>(&v1);
        const __half2* h2 = reinterpret_cast<const __half2*>(&v2);
        const __half2* h3 = reinterpret_cast<const __half2*>(&v3);
#pragma unroll
        for (int q = 0; q < 4; q++) {
            float2 f0 = __half22float2(h0[q]);
            float2 f1 = __half22float2(h1[q]);
            float2 f2 = __half22float2(h2[q]);
            float2 f3 = __half22float2(h3[q]);
            acc0[q * 2]     += f0.x + f2.x;
            acc0[q * 2 + 1] += f0.y + f2.y;
            acc1[q * 2]     += f1.x + f3.x;
            acc1[q * 2 + 1] += f1.y + f3.y;
        }
    }
    for (; i < e; i++) {
        int n0 = g_csr[i];
        uint4 v0 = *reinterpret_cast<const uint4*>(&g_y[(size_t)n0 * H_CH + p8]);
        const __half2* h0 = reinterpret_cast<const __half2*>(&v0);
#pragma unroll
        for (int q = 0; q < 4; q++) {
            float2 f0 = __half22float2(h0[q]);
            acc0[q * 2]     += f0.x;
            acc0[q * 2 + 1] += f0.y;
        }
    }
    float4 o0 = make_float4(acc0[0] + acc1[0], acc0[1] + acc1[1],
                            acc0[2] + acc1[2], acc0[3] + acc1[3]);
    float4 o1 = make_float4(acc0[4] + acc1[4], acc0[5] + acc1[5],
                            acc0[6] + acc1[6], acc0[7] + acc1[7]);
    *reinterpret_cast<float4*>(&g_agg[(size_t)node * H_CH + p8])     = o0;
    *reinterpret_cast<float4*>(&g_agg[(size_t)node * H_CH + p8 + 4]) = o1;
}

// ---------------- mlp1 rel: g_y(fp16) = xc @ W1_rel, node-range ----------------
__global__ void k_mlp1_rel(const float* __restrict__ x_in,
                           const float* __restrict__ W1_rel,
                           int node_base) {
    extern __shared__ float sm[];
    float* xs = sm;              // [64][96]
    float* Ws = sm + 64 * 96;    // [96][64]
    const int tid = threadIdx.x;
    const int node0 = node_base + blockIdx.x * 64;

    for (int i = tid; i < 96 * 64; i += 256) Ws[i] = W1_rel[i];
    for (int i = tid; i < 64 * 96; i += 256) {
        int n = i / 96, k = i - n * 96;
        int node = node0 + n;
        float v = 0.f;
        if (node < N_NODES)
            v = (k < 64) ? x_in[(size_t)node * 64 + k]
                         : g_edge_aggr[(size_t)node * EC + (k - 64)];
        xs[i] = v;
    }
    __syncthreads();

    const int og = tid & 15, ng = tid >> 4;
    const int j0 = og * 4, n0 = ng * 4;
    unsigned long long acc[4][2];
#pragma unroll
    for (int i = 0; i < 4; i++) { acc[i][0] = 0ull; acc[i][1] = 0ull; }

    for (int k4 = 0; k4 < 96; k4 += 4) {
        float4 a0 = *reinterpret_cast<const float4*>(&xs[(n0 + 0) * 96 + k4]);
        float4 a1 = *reinterpret_cast<const float4*>(&xs[(n0 + 1) * 96 + k4]);
        float4 a2 = *reinterpret_cast<const float4*>(&xs[(n0 + 2) * 96 + k4]);
        float4 a3 = *reinterpret_cast<const float4*>(&xs[(n0 + 3) * 96 + k4]);
        const float* p0 = &a0.x;
        const float* p1 = &a1.x;
        const float* p2 = &a2.x;
        const float* p3 = &a3.x;
#pragma unroll
        for (int j = 0; j < 4; j++) {
            ulonglong2 w = *reinterpret_cast<const ulonglong2*>(&Ws[(k4 + j) * 64 + j0]);
            unsigned long long b0 = bcast2(p0[j]);
            unsigned long long b1 = bcast2(p1[j]);
            unsigned long long b2 = bcast2(p2[j]);
            unsigned long long b3 = bcast2(p3[j]);
            ffma2(acc[0][0], b0, w.x);  ffma2(acc[0][1], b0, w.y);
            ffma2(acc[1][0], b1, w.x);  ffma2(acc[1][1], b1, w.y);
            ffma2(acc[2][0], b2, w.x);  ffma2(acc[2][1], b2, w.y);
            ffma2(acc[3][0], b3, w.x);  ffma2(acc[3][1], b3, w.y);
        }
    }

#pragma unroll
    for (int i = 0; i < 4; i++) {
        int node = node0 + n0 + i;
        if (node >= N_NODES) continue;
        float2 f0 = u2f(acc[i][0]), f1 = u2f(acc[i][1]);
        __half2 h0 = __floats2half2_rn(f0.x, f0.y);
        __half2 h1 = __floats2half2_rn(f1.x, f1.y);
        uint2 pk;
        pk.x = *reinterpret_cast<unsigned int*>(&h0);
        pk.y = *reinterpret_cast<unsigned int*>(&h1);
        *reinterpret_cast<uint2*>(&g_y[(size_t)node * 64 + j0]) = pk;
    }
}

// ---------------- mlp1 root: g_u = relu(xc @ W1_root + b1) ----------------
__global__ void k_mlp1_root(const float* __restrict__ x_in,
                            const float* __restrict__ W1_root,
                            const float* __restrict__ b1_root) {
    extern __shared__ float sm[];
    float* xs = sm;              // [64][96]
    float* Ws = sm + 64 * 96;    // [96][64]
    float* b1 = Ws + 96 * 64;    // [64]
    const int tid = threadIdx.x;
    const int node0 = blockIdx.x * 64;

    for (int i = tid; i < 96 * 64; i += 256) Ws[i] = W1_root[i];
    if (tid < 64) b1[tid] = b1_root[tid];
    for (int i = tid; i < 64 * 96; i += 256) {
        int n = i / 96, k = i - n * 96;
        int node = node0 + n;
        float v = 0.f;
        if (node < N_NODES)
            v = (k < 64) ? x_in[(size_t)node * 64 + k]
                         : g_edge_aggr[(size_t)node * EC + (k - 64)];
        xs[i] = v;
    }
    __syncthreads();

    const int og = tid & 15, ng = tid >> 4;
    const int j0 = og * 4, n0 = ng * 4;
    unsigned long long acc[4][2];
#pragma unroll
    for (int i = 0; i < 4; i++) { acc[i][0] = 0ull; acc[i][1] = 0ull; }

    for (int k4 = 0; k4 < 96; k4 += 4) {
        float4 a0 = *reinterpret_cast<const float4*>(&xs[(n0 + 0) * 96 + k4]);
        float4 a1 = *reinterpret_cast<const float4*>(&xs[(n0 + 1) * 96 + k4]);
        float4 a2 = *reinterpret_cast<const float4*>(&xs[(n0 + 2) * 96 + k4]);
        float4 a3 = *reinterpret_cast<const float4*>(&xs[(n0 + 3) * 96 + k4]);
        const float* p0 = &a0.x;
        const float* p1 = &a1.x;
        const float* p2 = &a2.x;
        const float* p3 = &a3.x;
#pragma unroll
        for (int j = 0; j < 4; j++) {
            ulonglong2 w = *reinterpret_cast<const ulonglong2*>(&Ws[(k4 + j) * 64 + j0]);
            unsigned long long b0 = bcast2(p0[j]);
            unsigned long long b1x = bcast2(p1[j]);
            unsigned long long b2 = bcast2(p2[j]);
            unsigned long long b3 = bcast2(p3[j]);
            ffma2(acc[0][0], b0, w.x);   ffma2(acc[0][1], b0, w.y);
            ffma2(acc[1][0], b1x, w.x);  ffma2(acc[1][1], b1x, w.y);
            ffma2(acc[2][0], b2, w.x);   ffma2(acc[2][1], b2, w.y);
            ffma2(acc[3][0], b3, w.x);   ffma2(acc[3][1], b3, w.y);
        }
    }

#pragma unroll
    for (int i = 0; i < 4; i++) {
        int node = node0 + n0 + i;
        if (node >= N_NODES) continue;
        float2 f0 = u2f(acc[i][0]), f1 = u2f(acc[i][1]);
        float4 o = make_float4(fmaxf(f0.x + b1[j0 + 0], 0.f),
                               fmaxf(f0.y + b1[j0 + 1], 0.f),
                               fmaxf(f1.x + b1[j0 + 2], 0.f),
                               fmaxf(f1.y + b1[j0 + 3], 0.f));
        *reinterpret_cast<float4*>(&g_u[(size_t)node * 64 + j0]) = o;
    }
}

// ---------------- mlp2: node-range + fused pooling on last layer ----------------
__global__ void k_node_mlp2(const float* __restrict__ b1_rel,
                            const float* __restrict__ W2_rel,
                            const float* __restrict__ W2_root,
                            const float* __restrict__ b2_rel,
                            const float* __restrict__ b2_root,
                            const int* __restrict__ batch,
                            int final_layer, int node_base) {
    extern __shared__ float sm[];
    float* As = sm;               // [64][128]
    float* Ws = sm + 64 * 128;    // [128][64]
    float* b2 = Ws + 128 * 64;    // [64]
    const int tid = threadIdx.x;
    const int node0 = node_base + blockIdx.x * 64;

    for (int i = tid; i < 128 * 64; i += 256)
        Ws[i] = (i < 64 * 64) ? W2_rel[i] : W2_root[i - 64 * 64];
    if (tid < 64) b2[tid] = b2_rel[tid] + b2_root[tid];
    for (int i = tid; i < 64 * 128; i += 256) {
        int n = i >> 7, k = i & 127;
        int node = node0 + n;
        float v = 0.f;
        if (node < N_NODES) {
            if (k < 64) v = fmaxf(g_agg[(size_t)node * 64 + k] + __ldg(&b1_rel[k]), 0.f);
            else        v = g_u[(size_t)node * 64 + (k - 64)];
        }
        As[i] = v;
    }
    __syncthreads();

    const int og = tid & 15, ng = tid >> 4;
    const int j0 = og * 4, n0 = ng * 4;
    unsigned long long acc[4][2];
#pragma unroll
    for (int i = 0; i < 4; i++) { acc[i][0] = 0ull; acc[i][1] = 0ull; }

    for (int k4 = 0; k4 < 128; k4 += 4) {
        float4 a0 = *reinterpret_cast<const float4*>(&As[(n0 + 0) * 128 + k4]);
        float4 a1 = *reinterpret_cast<const float4*>(&As[(n0 + 1) * 128 + k4]);
        float4 a2 = *reinterpret_cast<const float4*>(&As[(n0 + 2) * 128 + k4]);
        float4 a3 = *reinterpret_cast<const float4*>(&As[(n0 + 3) * 128 + k4]);
        const float* p0 = &a0.x;
        const float* p1 = &a1.x;
        const float* p2 = &a2.x;
        const float* p3 = &a3.x;
#pragma unroll
        for (int j = 0; j < 4; j++) {
            ulonglong2 w = *reinterpret_cast<const ulonglong2*>(&Ws[(k4 + j) * 64 + j0]);
            unsigned long long b0 = bcast2(p0[j]);
            unsigned long long b1 = bcast2(p1[j]);
            unsigned long long b2x = bcast2(p2[j]);
            unsigned long long b3 = bcast2(p3[j]);
            ffma2(acc[0][0], b0, w.x);   ffma2(acc[0][1], b0, w.y);
            ffma2(acc[1][0], b1, w.x);   ffma2(acc[1][1], b1, w.y);
            ffma2(acc[2][0], b2x, w.x);  ffma2(acc[2][1], b2x, w.y);
            ffma2(acc[3][0], b3, w.x);   ffma2(acc[3][1], b3, w.y);
        }
    }

#pragma unroll
    for (int i = 0; i < 4; i++) {
        int node = node0 + n0 + i;
        if (node >= N_NODES) continue;
        float2 f0 = u2f(acc[i][0]), f1 = u2f(acc[i][1]);
        float4 o = make_float4(fmaxf(f0.x + b2[j0 + 0], 0.f),
                               fmaxf(f0.y + b2[j0 + 1], 0.f),
                               fmaxf(f1.x + b2[j0 + 2], 0.f),
                               fmaxf(f1.y + b2[j0 + 3], 0.f));
        if (final_layer) {
            int b = batch[node];
            red4(&g_pooled[(size_t)b * 64 + j0], o);
        } else {
            *reinterpret_cast<float4*>(&g_x[(size_t)node * 64 + j0]) = o;
        }
    }
}

// ---------------- final MLP ----------------
__global__ void k_final(const float* __restrict__ W1, const float* __restrict__ b1,
                        const float* __restrict__ W2, const float* __restrict__ b2,
                        float* __restrict__ out) {
    __shared__ float pr[64];
    __shared__ float h[64];
    int g = blockIdx.x;
    int j = threadIdx.x;
    pr[j] = g_pooled[g * 64 + j];
    __syncthreads();
    float s = b1[j];
#pragma unroll 8
    for (int k = 0; k < 64; k++) s = fmaf(pr[k], W1[k * 64 + j], s);
    h[j] = fmaxf(s, 0.f);
    __syncthreads();
    if (j < OUT_CH) {
        float s2 = b2[j];
#pragma unroll 8
        for (int k = 0; k < 64; k++) s2 = fmaf(h[k], W2[k * OUT_CH + j], s2);
        out[g * OUT_CH + j] = s2;
    }
}

// ---------------- launch ----------------
extern "C" void kernel_launch(void* const* d_in, const int* in_sizes, int n_in,
                              void* d_out, int out_size) {
    const float* x         = (const float*)d_in[0];
    const float* edge_attr = (const float*)d_in[1];
    const float* relW1[2]  = {(const float*)d_in[2],  (const float*)d_in[10]};
    const float* relb1[2]  = {(const float*)d_in[3],  (const float*)d_in[11]};
    const float* relW2[2]  = {(const float*)d_in[4],  (const float*)d_in[12]};
    const float* relb2[2]  = {(const float*)d_in[5],  (const float*)d_in[13]};
    const float* rootW1[2] = {(const float*)d_in[6],  (const float*)d_in[14]};
    const float* rootb1[2] = {(const float*)d_in[7],  (const float*)d_in[15]};
    const float* rootW2[2] = {(const float*)d_in[8],  (const float*)d_in[16]};
    const float* rootb2[2] = {(const float*)d_in[9],  (const float*)d_in[17]};
    const float* finW1 = (const float*)d_in[18];
    const float* finb1 = (const float*)d_in[19];
    const float* finW2 = (const float*)d_in[20];
    const float* finb2 = (const float*)d_in[21];
    const int* edge_index = (const int*)d_in[22];
    const int* batch      = (const int*)d_in[23];
    float* out = (float*)d_out;

    float *p_ea, *p_x, *p_pooled;
    int *p_icnt;
    cudaGetSymbolAddress((void**)&p_ea, g_edge_aggr);
    cudaGetSymbolAddress((void**)&p_x, g_x);
    cudaGetSymbolAddress((void**)&p_pooled, g_pooled);
    cudaGetSymbolAddress((void**)&p_icnt, g_icnt);

    const int SMEM_REL  = (64 * 96 + 96 * 64) * 4;
    const int SMEM_ROOT = (64 * 96 + 96 * 64 + 64) * 4;
    const int SMEM2     = (64 * 128 + 128 * 64 + 64) * 4;
    cudaFuncSetAttribute(k_mlp1_rel, cudaFuncAttributeMaxDynamicSharedMemorySize, SMEM_REL);
    cudaFuncSetAttribute(k_mlp1_root, cudaFuncAttributeMaxDynamicSharedMemorySize, SMEM_ROOT);
    cudaFuncSetAttribute(k_node_mlp2, cudaFuncAttributeMaxDynamicSharedMemorySize, SMEM2);

    static cudaStream_t s2 = nullptr;
    static cudaEvent_t ev[12];
    if (!s2) {
        cudaStreamCreateWithFlags(&s2, cudaStreamNonBlocking);
        for (int i = 0; i < 12; i++)
            cudaEventCreateWithFlags(&ev[i], cudaEventDisableTiming);
    }
    cudaEvent_t evF = ev[0], evJ = ev[1],
                evY0 = ev[2], evU0 = ev[3], evGB0 = ev[4],
                evXA0 = ev[5], evX0 = ev[6],
                evRA1 = ev[7], evYB1 = ev[8], evU1 = ev[9], evGB1 = ev[10],
                evEA = ev[11];

    const int NODE_BLOCKS = (N_NODES + 63) / 64;                  // 782
    const int REL_A = NODE_HALF / 64;                              // 438
    const int REL_B = (N_NODES - NODE_HALF + 63) / 64;             // 344
    const int MLP2_A = REL_A, MLP2_B = REL_B;
    const int GA = NODE_HALF / 32;                                 // 876
    const int GB = (N_NODES - NODE_HALF + 31) / 32;                // 687
    const int EDGE_BLOCKS = (N_EDGES + 255) / 256;

    // ---- fork: CSR build on side stream ----
    cudaEventRecord(evF, 0);
    cudaStreamWaitEvent(s2, evF, 0);
    cudaMemsetAsync(p_icnt, 0, 2 * N_NODES * sizeof(int), s2);
    k_hist<<<EDGE_BLOCKS, 256, 0, s2>>>(edge_index);
    k_scan<<<1, 1024, 0, s2>>>();
    k_fill<<<EDGE_BLOCKS, 256, 0, s2>>>(edge_index);
    cudaEventRecord(evJ, s2);

    // ---- main prologue ----
    cudaMemsetAsync(p_ea, 0, N_NODES * EC * sizeof(float), 0);
    cudaMemsetAsync(p_pooled, 0, G_GRAPHS * H_CH * sizeof(float), 0);
    k_edge_aggr<<<(N_EDGES / 4 * 8 + 255) / 256, 256>>>(edge_attr, edge_index, p_ea);
    cudaEventRecord(evEA, 0);

    // ======== layer 0 ========
    k_mlp1_rel<<<NODE_BLOCKS, 256, SMEM_REL>>>(x, relW1[0], 0);
    cudaEventRecord(evY0, 0);

    // s2: root(l0) gated only by edge_aggr; gatherB(l0) gated by rel(l0)
    cudaStreamWaitEvent(s2, evEA, 0);
    k_mlp1_root<<<NODE_BLOCKS, 256, SMEM_ROOT, s2>>>(x, rootW1[0], rootb1[0]);
    cudaEventRecord(evU0, s2);
    cudaStreamWaitEvent(s2, evY0, 0);
    k_gather<<<GB, 256, 0, s2>>>(NODE_HALF, N_NODES);
    cudaEventRecord(evGB0, s2);

    // main: gatherA(l0) + mlp2A(l0) + mlp2B(l0)
    cudaStreamWaitEvent(0, evJ, 0);
    k_gather<<<GA, 256>>>(0, NODE_HALF);
    cudaStreamWaitEvent(0, evU0, 0);
    k_node_mlp2<<<MLP2_A, 256, SMEM2>>>(relb1[0], relW2[0], rootW2[0],
                                        relb2[0], rootb2[0], batch, 0, 0);
    cudaEventRecord(evXA0, 0);
    cudaStreamWaitEvent(0, evGB0, 0);
    k_node_mlp2<<<MLP2_B, 256, SMEM2>>>(relb1[0], relW2[0], rootW2[0],
                                        relb2[0], rootb2[0], batch, 0, NODE_HALF);
    cudaEventRecord(evX0, 0);

    // ======== layer 1 ========
    // s2: relA(l1) hidden under main's mlp2B(l0)
    cudaStreamWaitEvent(s2, evXA0, 0);
    k_mlp1_rel<<<REL_A, 256, SMEM_REL, s2>>>(p_x, relW1[1], 0);
    cudaEventRecord(evRA1, s2);
    // s2: root(l1) then gatherB(l1)
    cudaStreamWaitEvent(s2, evX0, 0);
    k_mlp1_root<<<NODE_BLOCKS, 256, SMEM_ROOT, s2>>>(p_x, rootW1[1], rootb1[1]);
    cudaEventRecord(evU1, s2);

    // main: relB(l1)
    k_mlp1_rel<<<REL_B, 256, SMEM_REL>>>(p_x, relW1[1], NODE_HALF);
    cudaEventRecord(evYB1, 0);

    // s2: gatherB(l1) needs relA (in-order) + relB (evYB1)
    cudaStreamWaitEvent(s2, evYB1, 0);
    k_gather<<<GB, 256, 0, s2>>>(NODE_HALF, N_NODES);
    cudaEventRecord(evGB1, s2);

    // main: gatherA(l1) needs relA (evRA1) + relB (in-order)
    cudaStreamWaitEvent(0, evRA1, 0);
    k_gather<<<GA, 256>>>(0, NODE_HALF);
    cudaStreamWaitEvent(0, evU1, 0);
    k_node_mlp2<<<MLP2_A, 256, SMEM2>>>(relb1[1], relW2[1], rootW2[1],
                                        relb2[1], rootb2[1], batch, 1, 0);
    cudaStreamWaitEvent(0, evGB1, 0);
    k_node_mlp2<<<MLP2_B, 256, SMEM2>>>(relb1[1], relW2[1], rootW2[1],
                                        relb2[1], rootb2[1], batch, 1, NODE_HALF);

    k_final<<<G_GRAPHS, 64>>>(finW1, finb1, finW2, finb2, out);
}

// round 16
// speedup vs baseline: 1.1154x; 1.0072x over previous
#include <cuda_runtime.h>
#include <cuda_fp16.h>
#include <cstdint>

#define N_NODES 50000
#define N_EDGES 1600000
#define G_GRAPHS 256
#define IN_CH 64
#define EC 32
#define H_CH 64
#define OUT_CH 10

#define NODE_HALF 28032   // alpha=0.56 split, multiple of 64

// ---------------- scratch ----------------
__device__ float  g_edge_aggr[N_NODES * EC];
__device__ __half g_y[N_NODES * H_CH];
__device__ float  g_u[N_NODES * H_CH];
__device__ float  g_agg[N_NODES * H_CH];
__device__ float  g_x[N_NODES * H_CH];
__device__ float  g_pooled[G_GRAPHS * H_CH];
__device__ int    g_icnt[2 * N_NODES];
__device__ int    g_off[N_NODES + 1];
__device__ int    g_csr[N_EDGES];

// ---------------- PTX helpers ----------------
__device__ __forceinline__ void red4(float* addr, float4 v) {
    asm volatile("red.global.add.v4.f32 [%0], {%1,%2,%3,%4};"
                 :: "l"(addr), "f"(v.x), "f"(v.y), "f"(v.z), "f"(v.w)
                 : "memory");
}
__device__ __forceinline__ void ffma2(unsigned long long& d,
                                      unsigned long long a, unsigned long long b) {
    asm("fma.rn.f32x2 %0, %1, %2, %0;" : "+l"(d) : "l"(a), "l"(b));
}
__device__ __forceinline__ unsigned long long bcast2(float a) {
    unsigned long long r;
    asm("mov.b64 %0, {%1, %1};" : "=l"(r) : "f"(a));
    return r;
}
__device__ __forceinline__ float2 u2f(unsigned long long v) {
    float2 f;
    asm("mov.b64 {%0, %1}, %2;" : "=f"(f.x), "=f"(f.y) : "l"(v));
    return f;
}

// ---------------- CSR build ----------------
__global__ void k_hist(const int* __restrict__ edge_index) {
    int e = blockIdx.x * blockDim.x + threadIdx.x;
    if (e >= N_EDGES) return;
    atomicAdd(&g_icnt[edge_index[N_EDGES + e]], 1);
}

__global__ void k_scan() {
    __shared__ int wsum[32];
    __shared__ int chunk_base;
    int tid = threadIdx.x, lane = tid & 31, wid = tid >> 5;
    if (tid == 0) chunk_base = 0;
    for (int start = 0; start < N_NODES; start += 4096) {
        __syncthreads();
        int idx = start + tid * 4;
        int a0 = 0, a1 = 0, a2 = 0, a3 = 0;
        if (idx + 3 < N_NODES) {
            int4 t = *reinterpret_cast<const int4*>(&g_icnt[idx]);
            a0 = t.x; a1 = t.y; a2 = t.z; a3 = t.w;
        } else if (idx < N_NODES) {
            a0 = g_icnt[idx];
            if (idx + 1 < N_NODES) a1 = g_icnt[idx + 1];
            if (idx + 2 < N_NODES) a2 = g_icnt[idx + 2];
        }
        int v = a0 + a1 + a2 + a3;
        int x = v;
#pragma unroll
        for (int d = 1; d < 32; d <<= 1) {
            int y = __shfl_up_sync(0xffffffffu, x, d);
            if (lane >= d) x += y;
        }
        if (lane == 31) wsum[wid] = x;
        __syncthreads();
        if (wid == 0) {
            int s = wsum[lane];
#pragma unroll
            for (int d = 1; d < 32; d <<= 1) {
                int y = __shfl_up_sync(0xffffffffu, s, d);
                if (lane >= d) s += y;
            }
            wsum[lane] = s;
        }
        __syncthreads();
        int wbase = (wid > 0) ? wsum[wid - 1] : 0;
        int base = chunk_base + wbase + x - v;
        if (idx < N_NODES)     g_off[idx]     = base;
        if (idx + 1 < N_NODES) g_off[idx + 1] = base + a0;
        if (idx + 2 < N_NODES) g_off[idx + 2] = base + a0 + a1;
        if (idx + 3 < N_NODES) g_off[idx + 3] = base + a0 + a1 + a2;
        __syncthreads();
        if (tid == 0) chunk_base += wsum[31];
    }
    __syncthreads();
    if (tid == 0) g_off[N_NODES] = chunk_base;
}

__global__ void k_fill(const int* __restrict__ edge_index) {
    int e = blockIdx.x * blockDim.x + threadIdx.x;
    if (e >= N_EDGES) return;
    int c = edge_index[N_EDGES + e];
    int pos = g_off[c] + atomicAdd(&g_icnt[N_NODES + c], 1);
    g_csr[pos] = edge_index[e];
}

// ---------------- edge_attr aggregation (4 edges/thread) ----------------
__global__ void k_edge_aggr(const float* __restrict__ edge_attr,
                            const int* __restrict__ edge_index,
                            float* __restrict__ out) {
    const int Q = N_EDGES / 4;
    int tid = blockIdx.x * blockDim.x + threadIdx.x;
    int e = tid >> 3, p4 = (tid & 7) * 4;
    if (e >= Q) return;
    int e1 = e + Q, e2 = e + 2 * Q, e3 = e + 3 * Q;
    int r0 = edge_index[e],  r1 = edge_index[e1];
    int r2 = edge_index[e2], r3 = edge_index[e3];
    float4 v0 = *reinterpret_cast<const float4*>(edge_attr + (size_t)e  * EC + p4);
    float4 v1 = *reinterpret_cast<const float4*>(edge_attr + (size_t)e1 * EC + p4);
    float4 v2 = *reinterpret_cast<const float4*>(edge_attr + (size_t)e2 * EC + p4);
    float4 v3 = *reinterpret_cast<const float4*>(edge_attr + (size_t)e3 * EC + p4);
    red4(out + (size_t)r0 * EC + p4, v0);
    red4(out + (size_t)r1 * EC + p4, v1);
    red4(out + (size_t)r2 * EC + p4, v2);
    red4(out + (size_t)r3 * EC + p4, v3);
}

// ---------------- CSR gather: 8 threads/node, unroll 4, node-range ----------------
__global__ void k_gather(int node_base, int node_end) {
    int tid = threadIdx.x;
    int node = node_base + blockIdx.x * 32 + (tid >> 3);
    int p8 = (tid & 7) * 8;
    if (node >= node_end) return;
    int s = g_off[node], e = g_off[node + 1];
    float acc0[8], acc1[8];
#pragma unroll
    for (int j = 0; j < 8; j++) { acc0[j] = 0.f; acc1[j] = 0.f; }

    int i = s;
    for (; i + 4 <= e; i += 4) {
        int n0 = g_csr[i], n1 = g_csr[i + 1], n2 = g_csr[i + 2], n3 = g_csr[i + 3];
        uint4 v0 = *reinterpret_cast<const uint4*>(&g_y[(size_t)n0 * H_CH + p8]);
        uint4 v1 = *reinterpret_cast<const uint4*>(&g_y[(size_t)n1 * H_CH + p8]);
        uint4 v2 = *reinterpret_cast<const uint4*>(&g_y[(size_t)n2 * H_CH + p8]);
        uint4 v3 = *reinterpret_cast<const uint4*>(&g_y[(size_t)n3 * H_CH + p8]);
        const __half2* h0 = reinterpret_cast<const __half2*>(&v0);
        const __half2* h1 = reinterpret_cast<const __half2*>(&v1);
        const __half2* h2 = reinterpret_cast<const __half2*>(&v2);
        const __half2* h3 = reinterpret_cast<const __half2*>(&v3);
#pragma unroll
        for (int q = 0; q < 4; q++) {
            float2 f0 = __half22float2(h0[q]);
            float2 f1 = __half22float2(h1[q]);
            float2 f2 = __half22float2(h2[q]);
            float2 f3 = __half22float2(h3[q]);
            acc0[q * 2]     += f0.x + f2.x;
            acc0[q * 2 + 1] += f0.y + f2.y;
            acc1[q * 2]     += f1.x + f3.x;
            acc1[q * 2 + 1] += f1.y + f3.y;
        }
    }
    for (; i < e; i++) {
        int n0 = g_csr[i];
        uint4 v0 = *reinterpret_cast<const uint4*>(&g_y[(size_t)n0 * H_CH + p8]);
        const __half2* h0 = reinterpret_cast<const __half2*>(&v0);
#pragma unroll
        for (int q = 0; q < 4; q++) {
            float2 f0 = __half22float2(h0[q]);
            acc0[q * 2]     += f0.x;
            acc0[q * 2 + 1] += f0.y;
        }
    }
    float4 o0 = make_float4(acc0[0] + acc1[0], acc0[1] + acc1[1],
                            acc0[2] + acc1[2], acc0[3] + acc1[3]);
    float4 o1 = make_float4(acc0[4] + acc1[4], acc0[5] + acc1[5],
                            acc0[6] + acc1[6], acc0[7] + acc1[7]);
    *reinterpret_cast<float4*>(&g_agg[(size_t)node * H_CH + p8])     = o0;
    *reinterpret_cast<float4*>(&g_agg[(size_t)node * H_CH + p8 + 4]) = o1;
}

// ---------------- mlp1 rel: g_y(fp16) = xc @ W1_rel, node-range ----------------
__global__ void k_mlp1_rel(const float* __restrict__ x_in,
                           const float* __restrict__ W1_rel,
                           int node_base) {
    extern __shared__ float sm[];
    float* xs = sm;              // [64][96]
    float* Ws = sm + 64 * 96;    // [96][64]
    const int tid = threadIdx.x;
    const int node0 = node_base + blockIdx.x * 64;

    for (int i = tid; i < 96 * 64; i += 256) Ws[i] = W1_rel[i];
    for (int i = tid; i < 64 * 96; i += 256) {
        int n = i / 96, k = i - n * 96;
        int node = node0 + n;
        float v = 0.f;
        if (node < N_NODES)
            v = (k < 64) ? x_in[(size_t)node * 64 + k]
                         : g_edge_aggr[(size_t)node * EC + (k - 64)];
        xs[i] = v;
    }
    __syncthreads();

    const int og = tid & 15, ng = tid >> 4;
    const int j0 = og * 4, n0 = ng * 4;
    unsigned long long acc[4][2];
#pragma unroll
    for (int i = 0; i < 4; i++) { acc[i][0] = 0ull; acc[i][1] = 0ull; }

    for (int k4 = 0; k4 < 96; k4 += 4) {
        float4 a0 = *reinterpret_cast<const float4*>(&xs[(n0 + 0) * 96 + k4]);
        float4 a1 = *reinterpret_cast<const float4*>(&xs[(n0 + 1) * 96 + k4]);
        float4 a2 = *reinterpret_cast<const float4*>(&xs[(n0 + 2) * 96 + k4]);
        float4 a3 = *reinterpret_cast<const float4*>(&xs[(n0 + 3) * 96 + k4]);
        const float* p0 = &a0.x;
        const float* p1 = &a1.x;
        const float* p2 = &a2.x;
        const float* p3 = &a3.x;
#pragma unroll
        for (int j = 0; j < 4; j++) {
            ulonglong2 w = *reinterpret_cast<const ulonglong2*>(&Ws[(k4 + j) * 64 + j0]);
            unsigned long long b0 = bcast2(p0[j]);
            unsigned long long b1 = bcast2(p1[j]);
            unsigned long long b2 = bcast2(p2[j]);
            unsigned long long b3 = bcast2(p3[j]);
            ffma2(acc[0][0], b0, w.x);  ffma2(acc[0][1], b0, w.y);
            ffma2(acc[1][0], b1, w.x);  ffma2(acc[1][1], b1, w.y);
            ffma2(acc[2][0], b2, w.x);  ffma2(acc[2][1], b2, w.y);
            ffma2(acc[3][0], b3, w.x);  ffma2(acc[3][1], b3, w.y);
        }
    }

#pragma unroll
    for (int i = 0; i < 4; i++) {
        int node = node0 + n0 + i;
        if (node >= N_NODES) continue;
        float2 f0 = u2f(acc[i][0]), f1 = u2f(acc[i][1]);
        __half2 h0 = __floats2half2_rn(f0.x, f0.y);
        __half2 h1 = __floats2half2_rn(f1.x, f1.y);
        uint2 pk;
        pk.x = *reinterpret_cast<unsigned int*>(&h0);
        pk.y = *reinterpret_cast<unsigned int*>(&h1);
        *reinterpret_cast<uint2*>(&g_y[(size_t)node * 64 + j0]) = pk;
    }
}

// ---------------- mlp1 root: g_u = relu(xc @ W1_root + b1), node-range ----------------
__global__ void k_mlp1_root(const float* __restrict__ x_in,
                            const float* __restrict__ W1_root,
                            const float* __restrict__ b1_root,
                            int node_base) {
    extern __shared__ float sm[];
    float* xs = sm;              // [64][96]
    float* Ws = sm + 64 * 96;    // [96][64]
    float* b1 = Ws + 96 * 64;    // [64]
    const int tid = threadIdx.x;
    const int node0 = node_base + blockIdx.x * 64;

    for (int i = tid; i < 96 * 64; i += 256) Ws[i] = W1_root[i];
    if (tid < 64) b1[tid] = b1_root[tid];
    for (int i = tid; i < 64 * 96; i += 256) {
        int n = i / 96, k = i - n * 96;
        int node = node0 + n;
        float v = 0.f;
        if (node < N_NODES)
            v = (k < 64) ? x_in[(size_t)node * 64 + k]
                         : g_edge_aggr[(size_t)node * EC + (k - 64)];
        xs[i] = v;
    }
    __syncthreads();

    const int og = tid & 15, ng = tid >> 4;
    const int j0 = og * 4, n0 = ng * 4;
    unsigned long long acc[4][2];
#pragma unroll
    for (int i = 0; i < 4; i++) { acc[i][0] = 0ull; acc[i][1] = 0ull; }

    for (int k4 = 0; k4 < 96; k4 += 4) {
        float4 a0 = *reinterpret_cast<const float4*>(&xs[(n0 + 0) * 96 + k4]);
        float4 a1 = *reinterpret_cast<const float4*>(&xs[(n0 + 1) * 96 + k4]);
        float4 a2 = *reinterpret_cast<const float4*>(&xs[(n0 + 2) * 96 + k4]);
        float4 a3 = *reinterpret_cast<const float4*>(&xs[(n0 + 3) * 96 + k4]);
        const float* p0 = &a0.x;
        const float* p1 = &a1.x;
        const float* p2 = &a2.x;
        const float* p3 = &a3.x;
#pragma unroll
        for (int j = 0; j < 4; j++) {
            ulonglong2 w = *reinterpret_cast<const ulonglong2*>(&Ws[(k4 + j) * 64 + j0]);
            unsigned long long b0 = bcast2(p0[j]);
            unsigned long long b1x = bcast2(p1[j]);
            unsigned long long b2 = bcast2(p2[j]);
            unsigned long long b3 = bcast2(p3[j]);
            ffma2(acc[0][0], b0, w.x);   ffma2(acc[0][1], b0, w.y);
            ffma2(acc[1][0], b1x, w.x);  ffma2(acc[1][1], b1x, w.y);
            ffma2(acc[2][0], b2, w.x);   ffma2(acc[2][1], b2, w.y);
            ffma2(acc[3][0], b3, w.x);   ffma2(acc[3][1], b3, w.y);
        }
    }

#pragma unroll
    for (int i = 0; i < 4; i++) {
        int node = node0 + n0 + i;
        if (node >= N_NODES) continue;
        float2 f0 = u2f(acc[i][0]), f1 = u2f(acc[i][1]);
        float4 o = make_float4(fmaxf(f0.x + b1[j0 + 0], 0.f),
                               fmaxf(f0.y + b1[j0 + 1], 0.f),
                               fmaxf(f1.x + b1[j0 + 2], 0.f),
                               fmaxf(f1.y + b1[j0 + 3], 0.f));
        *reinterpret_cast<float4*>(&g_u[(size_t)node * 64 + j0]) = o;
    }
}

// ---------------- mlp2: node-range + fused pooling on last layer ----------------
__global__ void k_node_mlp2(const float* __restrict__ b1_rel,
                            const float* __restrict__ W2_rel,
                            const float* __restrict__ W2_root,
                            const float* __restrict__ b2_rel,
                            const float* __restrict__ b2_root,
                            const int* __restrict__ batch,
                            int final_layer, int node_base) {
    extern __shared__ float sm[];
    float* As = sm;               // [64][128]
    float* Ws = sm + 64 * 128;    // [128][64]
    float* b2 = Ws + 128 * 64;    // [64]
    const int tid = threadIdx.x;
    const int node0 = node_base + blockIdx.x * 64;

    for (int i = tid; i < 128 * 64; i += 256)
        Ws[i] = (i < 64 * 64) ? W2_rel[i] : W2_root[i - 64 * 64];
    if (tid < 64) b2[tid] = b2_rel[tid] + b2_root[tid];
    for (int i = tid; i < 64 * 128; i += 256) {
        int n = i >> 7, k = i & 127;
        int node = node0 + n;
        float v = 0.f;
        if (node < N_NODES) {
            if (k < 64) v = fmaxf(g_agg[(size_t)node * 64 + k] + __ldg(&b1_rel[k]), 0.f);
            else        v = g_u[(size_t)node * 64 + (k - 64)];
        }
        As[i] = v;
    }
    __syncthreads();

    const int og = tid & 15, ng = tid >> 4;
    const int j0 = og * 4, n0 = ng * 4;
    unsigned long long acc[4][2];
#pragma unroll
    for (int i = 0; i < 4; i++) { acc[i][0] = 0ull; acc[i][1] = 0ull; }

    for (int k4 = 0; k4 < 128; k4 += 4) {
        float4 a0 = *reinterpret_cast<const float4*>(&As[(n0 + 0) * 128 + k4]);
        float4 a1 = *reinterpret_cast<const float4*>(&As[(n0 + 1) * 128 + k4]);
        float4 a2 = *reinterpret_cast<const float4*>(&As[(n0 + 2) * 128 + k4]);
        float4 a3 = *reinterpret_cast<const float4*>(&As[(n0 + 3) * 128 + k4]);
        const float* p0 = &a0.x;
        const float* p1 = &a1.x;
        const float* p2 = &a2.x;
        const float* p3 = &a3.x;
#pragma unroll
        for (int j = 0; j < 4; j++) {
            ulonglong2 w = *reinterpret_cast<const ulonglong2*>(&Ws[(k4 + j) * 64 + j0]);
            unsigned long long b0 = bcast2(p0[j]);
            unsigned long long b1 = bcast2(p1[j]);
            unsigned long long b2x = bcast2(p2[j]);
            unsigned long long b3 = bcast2(p3[j]);
            ffma2(acc[0][0], b0, w.x);   ffma2(acc[0][1], b0, w.y);
            ffma2(acc[1][0], b1, w.x);   ffma2(acc[1][1], b1, w.y);
            ffma2(acc[2][0], b2x, w.x);  ffma2(acc[2][1], b2x, w.y);
            ffma2(acc[3][0], b3, w.x);   ffma2(acc[3][1], b3, w.y);
        }
    }

#pragma unroll
    for (int i = 0; i < 4; i++) {
        int node = node0 + n0 + i;
        if (node >= N_NODES) continue;
        float2 f0 = u2f(acc[i][0]), f1 = u2f(acc[i][1]);
        float4 o = make_float4(fmaxf(f0.x + b2[j0 + 0], 0.f),
                               fmaxf(f0.y + b2[j0 + 1], 0.f),
                               fmaxf(f1.x + b2[j0 + 2], 0.f),
                               fmaxf(f1.y + b2[j0 + 3], 0.f));
        if (final_layer) {
            int b = batch[node];
            red4(&g_pooled[(size_t)b * 64 + j0], o);
        } else {
            *reinterpret_cast<float4*>(&g_x[(size_t)node * 64 + j0]) = o;
        }
    }
}

// ---------------- final MLP ----------------
__global__ void k_final(const float* __restrict__ W1, const float* __restrict__ b1,
                        const float* __restrict__ W2, const float* __restrict__ b2,
                        float* __restrict__ out) {
    __shared__ float pr[64];
    __shared__ float h[64];
    int g = blockIdx.x;
    int j = threadIdx.x;
    pr[j] = g_pooled[g * 64 + j];
    __syncthreads();
    float s = b1[j];
#pragma unroll 8
    for (int k = 0; k < 64; k++) s = fmaf(pr[k], W1[k * 64 + j], s);
    h[j] = fmaxf(s, 0.f);
    __syncthreads();
    if (j < OUT_CH) {
        float s2 = b2[j];
#pragma unroll 8
        for (int k = 0; k < 64; k++) s2 = fmaf(h[k], W2[k * OUT_CH + j], s2);
        out[g * OUT_CH + j] = s2;
    }
}

// ---------------- launch ----------------
extern "C" void kernel_launch(void* const* d_in, const int* in_sizes, int n_in,
                              void* d_out, int out_size) {
    const float* x         = (const float*)d_in[0];
    const float* edge_attr = (const float*)d_in[1];
    const float* relW1[2]  = {(const float*)d_in[2],  (const float*)d_in[10]};
    const float* relb1[2]  = {(const float*)d_in[3],  (const float*)d_in[11]};
    const float* relW2[2]  = {(const float*)d_in[4],  (const float*)d_in[12]};
    const float* relb2[2]  = {(const float*)d_in[5],  (const float*)d_in[13]};
    const float* rootW1[2] = {(const float*)d_in[6],  (const float*)d_in[14]};
    const float* rootb1[2] = {(const float*)d_in[7],  (const float*)d_in[15]};
    const float* rootW2[2] = {(const float*)d_in[8],  (const float*)d_in[16]};
    const float* rootb2[2] = {(const float*)d_in[9],  (const float*)d_in[17]};
    const float* finW1 = (const float*)d_in[18];
    const float* finb1 = (const float*)d_in[19];
    const float* finW2 = (const float*)d_in[20];
    const float* finb2 = (const float*)d_in[21];
    const int* edge_index = (const int*)d_in[22];
    const int* batch      = (const int*)d_in[23];
    float* out = (float*)d_out;

    float *p_ea, *p_x, *p_pooled;
    int *p_icnt;
    cudaGetSymbolAddress((void**)&p_ea, g_edge_aggr);
    cudaGetSymbolAddress((void**)&p_x, g_x);
    cudaGetSymbolAddress((void**)&p_pooled, g_pooled);
    cudaGetSymbolAddress((void**)&p_icnt, g_icnt);

    const int SMEM_REL  = (64 * 96 + 96 * 64) * 4;
    const int SMEM_ROOT = (64 * 96 + 96 * 64 + 64) * 4;
    const int SMEM2     = (64 * 128 + 128 * 64 + 64) * 4;
    cudaFuncSetAttribute(k_mlp1_rel, cudaFuncAttributeMaxDynamicSharedMemorySize, SMEM_REL);
    cudaFuncSetAttribute(k_mlp1_root, cudaFuncAttributeMaxDynamicSharedMemorySize, SMEM_ROOT);
    cudaFuncSetAttribute(k_node_mlp2, cudaFuncAttributeMaxDynamicSharedMemorySize, SMEM2);

    static cudaStream_t s2 = nullptr, s3 = nullptr;
    static cudaEvent_t ev[16];
    if (!s2) {
        cudaStreamCreateWithFlags(&s2, cudaStreamNonBlocking);
        cudaStreamCreateWithFlags(&s3, cudaStreamNonBlocking);
        for (int i = 0; i < 16; i++)
            cudaEventCreateWithFlags(&ev[i], cudaEventDisableTiming);
    }
    cudaEvent_t evF = ev[0], evJ = ev[1],
                evY0 = ev[2], evU0 = ev[3], evGB0 = ev[4],
                evXA0 = ev[5], evX0 = ev[6],
                evRA1 = ev[7], evYB1 = ev[8], evGB1 = ev[10],
                evEA = ev[11], evUA1 = ev[12], evUB1 = ev[13];

    const int NODE_BLOCKS = (N_NODES + 63) / 64;                  // 782
    const int REL_A = NODE_HALF / 64;                              // 438
    const int REL_B = (N_NODES - NODE_HALF + 63) / 64;             // 344
    const int MLP2_A = REL_A, MLP2_B = REL_B;
    const int GA = NODE_HALF / 32;                                 // 876
    const int GB = (N_NODES - NODE_HALF + 31) / 32;                // 687
    const int EDGE_BLOCKS = (N_EDGES + 255) / 256;

    // ---- fork: CSR build on side stream ----
    cudaEventRecord(evF, 0);
    cudaStreamWaitEvent(s2, evF, 0);
    cudaStreamWaitEvent(s3, evF, 0);
    cudaMemsetAsync(p_icnt, 0, 2 * N_NODES * sizeof(int), s2);
    k_hist<<<EDGE_BLOCKS, 256, 0, s2>>>(edge_index);
    k_scan<<<1, 1024, 0, s2>>>();
    k_fill<<<EDGE_BLOCKS, 256, 0, s2>>>(edge_index);
    cudaEventRecord(evJ, s2);

    // ---- main prologue ----
    cudaMemsetAsync(p_ea, 0, N_NODES * EC * sizeof(float), 0);
    cudaMemsetAsync(p_pooled, 0, G_GRAPHS * H_CH * sizeof(float), 0);
    k_edge_aggr<<<(N_EDGES / 4 * 8 + 255) / 256, 256>>>(edge_attr, edge_index, p_ea);
    cudaEventRecord(evEA, 0);

    // ======== layer 0 ========
    k_mlp1_rel<<<NODE_BLOCKS, 256, SMEM_REL>>>(x, relW1[0], 0);
    cudaEventRecord(evY0, 0);

    // s2: root(l0) gated only by edge_aggr; gatherB(l0) gated by rel(l0)
    cudaStreamWaitEvent(s2, evEA, 0);
    k_mlp1_root<<<NODE_BLOCKS, 256, SMEM_ROOT, s2>>>(x, rootW1[0], rootb1[0], 0);
    cudaEventRecord(evU0, s2);
    cudaStreamWaitEvent(s2, evY0, 0);
    k_gather<<<GB, 256, 0, s2>>>(NODE_HALF, N_NODES);
    cudaEventRecord(evGB0, s2);

    // main: gatherA(l0) + mlp2A(l0) + mlp2B(l0)
    cudaStreamWaitEvent(0, evJ, 0);
    k_gather<<<GA, 256>>>(0, NODE_HALF);
    cudaStreamWaitEvent(0, evU0, 0);
    k_node_mlp2<<<MLP2_A, 256, SMEM2>>>(relb1[0], relW2[0], rootW2[0],
                                        relb2[0], rootb2[0], batch, 0, 0);
    cudaEventRecord(evXA0, 0);
    cudaStreamWaitEvent(0, evGB0, 0);
    k_node_mlp2<<<MLP2_B, 256, SMEM2>>>(relb1[0], relW2[0], rootW2[0],
                                        relb2[0], rootb2[0], batch, 0, NODE_HALF);
    cudaEventRecord(evX0, 0);

    // ======== layer 1 ========
    // s2: relA(l1) + rootA(l1) hidden under main's mlp2B(l0)/relB(l1)
    cudaStreamWaitEvent(s2, evXA0, 0);
    k_mlp1_rel<<<REL_A, 256, SMEM_REL, s2>>>(p_x, relW1[1], 0);
    cudaEventRecord(evRA1, s2);
    k_mlp1_root<<<REL_A, 256, SMEM_ROOT, s2>>>(p_x, rootW1[1], rootb1[1], 0);
    cudaEventRecord(evUA1, s2);

    // s3: rootB(l1) concurrent with relA/relB
    cudaStreamWaitEvent(s3, evX0, 0);
    k_mlp1_root<<<REL_B, 256, SMEM_ROOT, s3>>>(p_x, rootW1[1], rootb1[1], NODE_HALF);
    cudaEventRecord(evUB1, s3);

    // main: relB(l1)
    k_mlp1_rel<<<REL_B, 256, SMEM_REL>>>(p_x, relW1[1], NODE_HALF);
    cudaEventRecord(evYB1, 0);

    // s2: gatherB(l1) needs relA (in-order) + relB (evYB1)
    cudaStreamWaitEvent(s2, evYB1, 0);
    k_gather<<<GB, 256, 0, s2>>>(NODE_HALF, N_NODES);
    cudaEventRecord(evGB1, s2);

    // main: gatherA(l1) needs relA (evRA1) + relB (in-order)
    cudaStreamWaitEvent(0, evRA1, 0);
    k_gather<<<GA, 256>>>(0, NODE_HALF);
    cudaStreamWaitEvent(0, evUA1, 0);
    k_node_mlp2<<<MLP2_A, 256, SMEM2>>>(relb1[1], relW2[1], rootW2[1],
                                        relb2[1], rootb2[1], batch, 1, 0);
    cudaStreamWaitEvent(0, evGB1, 0);
    cudaStreamWaitEvent(0, evUB1, 0);
    k_node_mlp2<<<MLP2_B, 256, SMEM2>>>(relb1[1], relW2[1], rootW2[1],
                                        relb2[1], rootb2[1], batch, 1, NODE_HALF);

    k_final<<<G_GRAPHS, 64>>>(finW1, finb1, finW2, finb2, out);
}